// round 2
// baseline (speedup 1.0000x reference)
#include <cuda_runtime.h>
#include <cstdint>

#define N_IN     256
#define DDEG     8
#define N_OUT    64
#define KDIM     (N_IN * DDEG)      // 2048
#define M_TILE   128
#define I_CHUNK  8
#define K_CHUNK  (I_CHUNK * DDEG)   // 64
#define N_CHUNKS (N_IN / I_CHUNK)   // 32
#define KSTEPS   (K_CHUNK / 8)      // 8 k-steps of k=8 per chunk
#define A_STRIDE 68                 // 64 + 4 pad: conflict-free LDS/STS (stride%32==4)

// W repacked into exact m16n8k8 .col B-fragment order, tf32-rounded.
// Layout (per chunk of 64 K): [ks(8)][q(4)][lane(32)][e(4)] floats.
__device__ float g_Bpack[KDIM * N_OUT];

__global__ void repack_kernel(const float* __restrict__ c_basis) {
    int idx = blockIdx.x * 256 + threadIdx.x;
    if (idx >= KDIM * N_OUT) return;
    int e    = idx & 3;
    int lane = (idx >> 2) & 31;
    int q    = (idx >> 7) & 3;
    int ks   = (idx >> 9) & 7;
    int ch   = idx >> 12;
    int p  = q * 4 + e;      // 0..15 = (ntile, j) pairs
    int nt = p >> 1;
    int j  = p & 1;
    int k  = ch * K_CHUNK + ks * 8 + (lane & 3) + 4 * j;  // B row (K)
    int n  = nt * 8 + (lane >> 2);                        // B col (N)
    int i  = k >> 3;   // input feature
    int d  = k & 7;    // degree index (P_{d+1})
    float w = c_basis[(n * N_IN + i) * DDEG + d];
    uint32_t tf;
    asm("cvt.rna.tf32.f32 %0, %1;" : "=r"(tf) : "f"(w));
    g_Bpack[idx] = __uint_as_float(tf);
}

extern __shared__ float smem[];

__global__ __launch_bounds__(256, 2)
void kan_main_kernel(const float* __restrict__ x, const float* __restrict__ bias,
                     float* __restrict__ y, int batch) {
    float* As = smem;                              // 128 * 68 = 8704 floats
    float* Bs = smem + M_TILE * A_STRIDE;          // 4096 floats
    float* Xs = Bs + KSTEPS * 4 * 32 * 4;          // 1024 floats

    int tid  = threadIdx.x;
    int lane = tid & 31, warp = tid >> 5;
    int rowBase = blockIdx.x * M_TILE;

    float acc[8][4] = {};

    // generation work mapping: conflict-free STS.128 (8 consecutive rows per phase)
    int rlow  = tid & 7;
    int il    = (tid >> 3) & 7;
    int rhigh = tid >> 6;

    for (int ch = 0; ch < N_CHUNKS; ch++) {
        __syncthreads();
        // ---- stage B chunk (fragment-packed, 16KB) ----
        {
            const float4* src = (const float4*)(g_Bpack + ch * (KSTEPS * 4 * 32 * 4));
            float4* dst = (float4*)Bs;
            #pragma unroll
            for (int r = 0; r < 4; r++) dst[tid + 256 * r] = src[tid + 256 * r];
        }
        // ---- stage x chunk: 128 rows x 8 feats, sector-exact coalesced float2 ----
        {
            const float2* x2 = (const float2*)x;
            float2* xd = (float2*)Xs;
            #pragma unroll
            for (int r = 0; r < 2; r++) {
                int idx = tid + 256 * r;
                int rl = idx >> 2, o = idx & 3;
                int rg = rowBase + rl; if (rg > batch - 1) rg = batch - 1;
                xd[idx] = x2[rg * (N_IN / 2) + ch * 4 + o];
            }
        }
        __syncthreads();
        // ---- generate A tile: tanh + Legendre recurrence, tf32-rounded ----
        #pragma unroll
        for (int rb = 0; rb < 4; rb++) {
            int rl = rlow + 8 * rhigh + 32 * rb;          // 0..127
            float xv = Xs[rl * 8 + il];
            float e2 = __expf(2.0f * xv);                 // accurate ~1e-6 tanh
            float t  = 1.0f - 2.0f / (e2 + 1.0f);
            float pv[8];
            pv[0] = t;
            float pprev = 1.0f, pcur = t;
            #pragma unroll
            for (int d = 1; d < 8; d++) {                 // P_{d+1}
                float kk = (float)(d + 1);
                float a_ = (2.0f * kk - 1.0f) / kk;
                float b_ = (kk - 1.0f) / kk;
                float pn = a_ * t * pcur - b_ * pprev;
                pv[d] = pn;
                pprev = pcur; pcur = pn;
            }
            uint32_t tf[8];
            #pragma unroll
            for (int d = 0; d < 8; d++)
                asm("cvt.rna.tf32.f32 %0, %1;" : "=r"(tf[d]) : "f"(pv[d]));
            float4* dst = (float4*)&As[rl * A_STRIDE + il * 8];
            dst[0] = make_float4(__uint_as_float(tf[0]), __uint_as_float(tf[1]),
                                 __uint_as_float(tf[2]), __uint_as_float(tf[3]));
            dst[1] = make_float4(__uint_as_float(tf[4]), __uint_as_float(tf[5]),
                                 __uint_as_float(tf[6]), __uint_as_float(tf[7]));
        }
        __syncthreads();
        // ---- MMA: 8 k-steps x 8 n-tiles of m16n8k8 tf32 ----
        {
            int gr = lane >> 2, c = lane & 3;
            const float* arow = &As[(warp * 16 + gr) * A_STRIDE + c];
            #pragma unroll
            for (int ks = 0; ks < KSTEPS; ks++) {
                uint32_t a0 = __float_as_uint(arow[ks * 8]);
                uint32_t a1 = __float_as_uint(arow[ks * 8 + 8 * A_STRIDE]);
                uint32_t a2 = __float_as_uint(arow[ks * 8 + 4]);
                uint32_t a3 = __float_as_uint(arow[ks * 8 + 8 * A_STRIDE + 4]);
                float4 bq[4];
                #pragma unroll
                for (int q = 0; q < 4; q++)
                    bq[q] = *(const float4*)&Bs[((ks * 4 + q) * 32 + lane) * 4];
                const uint32_t* bp = (const uint32_t*)bq;
                #pragma unroll
                for (int nt = 0; nt < 8; nt++) {
                    asm volatile(
                        "mma.sync.aligned.m16n8k8.row.col.f32.tf32.tf32.f32 "
                        "{%0,%1,%2,%3}, {%4,%5,%6,%7}, {%8,%9}, {%0,%1,%2,%3};"
                        : "+f"(acc[nt][0]), "+f"(acc[nt][1]),
                          "+f"(acc[nt][2]), "+f"(acc[nt][3])
                        : "r"(a0), "r"(a1), "r"(a2), "r"(a3),
                          "r"(bp[2 * nt]), "r"(bp[2 * nt + 1]));
                }
            }
        }
    }
    // ---- epilogue: bias add + vectorized store ----
    int gr = lane >> 2, tg = lane & 3;
    int r0 = rowBase + warp * 16 + gr;
    #pragma unroll
    for (int nt = 0; nt < 8; nt++) {
        int col = nt * 8 + 2 * tg;
        float b0 = bias[col], b1 = bias[col + 1];
        if (r0 < batch)
            *(float2*)&y[r0 * N_OUT + col] =
                make_float2(acc[nt][0] + b0, acc[nt][1] + b1);
        if (r0 + 8 < batch)
            *(float2*)&y[(r0 + 8) * N_OUT + col] =
                make_float2(acc[nt][2] + b0, acc[nt][3] + b1);
    }
}

extern "C" void kernel_launch(void* const* d_in, const int* in_sizes, int n_in,
                              void* d_out, int out_size) {
    const float* x       = (const float*)d_in[0];
    const float* c_basis = (const float*)d_in[1];
    const float* bias    = (const float*)d_in[2];
    float* y = (float*)d_out;
    int batch = in_sizes[0] / N_IN;

    const int smem_bytes = (M_TILE * A_STRIDE + KSTEPS * 4 * 32 * 4 + M_TILE * I_CHUNK)
                           * (int)sizeof(float);  // 55296
    cudaFuncSetAttribute(kan_main_kernel,
                         cudaFuncAttributeMaxDynamicSharedMemorySize, smem_bytes);

    repack_kernel<<<(KDIM * N_OUT + 255) / 256, 256>>>(c_basis);
    int grid = (batch + M_TILE - 1) / M_TILE;
    kan_main_kernel<<<grid, 256, smem_bytes>>>(x, bias, y, batch);
}

// round 4
// speedup vs baseline: 1.3632x; 1.3632x over previous
#include <cuda_runtime.h>
#include <cuda_fp16.h>
#include <cstdint>

#define N_IN     256
#define DDEG     8
#define N_OUT    64
#define M_TILE   128
#define N_CHUNKS 32

// smem byte offsets: A double-buffered 16KB each, B 8KB each
#define SMA(p)   ((p) * 16384)
#define SMB(p)   (32768 + (p) * 8192)
#define SM_TOTAL 49152

// B prepacked as exact per-chunk smem fragment images: 32 chunks x 4096 halves
__device__ __half g_Bpack[N_CHUNKS * 4096];

// Layout: [ch][ks(4)][ng(4)][lane(32)][e(8 halves)]; uint4 slot = frags of
// n-tiles {2ng, 2ng+1}: {nt0.b01, nt0.b23, nt1.b01, nt1.b23}
__global__ void repack_kernel(const float* __restrict__ c_basis) {
    int idx = blockIdx.x * 256 + threadIdx.x;          // 131072 total
    int e    = idx & 7;
    int lane = (idx >> 3) & 31;
    int ng   = (idx >> 8) & 3;
    int ks   = (idx >> 10) & 3;
    int ch   = idx >> 12;
    int nt = ng * 2 + (e >> 2);
    int bp = (e >> 1) & 1;                             // b01 vs b23 (k +8)
    int h  = e & 1;
    int k  = ks * 16 + bp * 8 + (lane & 3) * 2 + h;    // k within chunk
    int n  = nt * 8 + (lane >> 2);
    int kg = ch * 64 + k;
    int i = kg >> 3, d = kg & 7;
    g_Bpack[idx] = __float2half_rn(c_basis[(n * N_IN + i) * DDEG + d]);
}

#define MMA16816(ac, A0, A1, A2, A3, B0, B1)                                  \
    asm volatile(                                                             \
        "mma.sync.aligned.m16n8k16.row.col.f32.f16.f16.f32 "                  \
        "{%0,%1,%2,%3}, {%4,%5,%6,%7}, {%8,%9}, {%0,%1,%2,%3};"               \
        : "+f"((ac)[0]), "+f"((ac)[1]), "+f"((ac)[2]), "+f"((ac)[3])          \
        : "r"(A0), "r"(A1), "r"(A2), "r"(A3), "r"(B0), "r"(B1))

__device__ __forceinline__ void cp_async16(uint32_t saddr, const void* gptr) {
    asm volatile("cp.async.ca.shared.global [%0], [%1], 16;"
                 :: "r"(saddr), "l"(gptr) : "memory");
}

extern __shared__ __align__(128) char sm[];

__global__ __launch_bounds__(256, 2)
void kan_fp16_kernel(const float* __restrict__ x, const float* __restrict__ bias,
                     float* __restrict__ y, int batch) {
    const int tid  = threadIdx.x;
    const int lane = tid & 31;
    const int wid  = tid >> 5;
    const int wm   = wid & 3;          // m32 group (rows wm*32..+31)
    const int wn   = wid >> 2;         // n32 group (cols wn*32..+31)
    const int rowBase = blockIdx.x * M_TILE;
    const uint32_t sbase = (uint32_t)__cvta_generic_to_shared(sm);

    // ---- gen mapping: thread -> (row 0..127, half feats 0-3 / 4-7) ----
    const int grow = tid & 127;
    const int half = tid >> 7;
    const int mt = grow >> 4, rh = (grow >> 3) & 1, rq = grow & 7;
    int rg = rowBase + grow; if (rg > batch - 1) rg = batch - 1;
    const float* xrow = x + (size_t)rg * N_IN + half * 4;

    // ---- consumer fragment indices ----
    const int c  = lane & 3;
    const int fr = lane >> 2;

    float acc[2][4][4] = {};

    // ---- prolog: cp.async stage B(0), prefetch x(0) ----
    {
        const char* src = (const char*)g_Bpack;
        cp_async16(sbase + SMB(0) + tid * 16,         src + tid * 16);
        cp_async16(sbase + SMB(0) + (tid + 256) * 16, src + (tid + 256) * 16);
        asm volatile("cp.async.commit_group;" ::: "memory");
    }
    float4 xv = *(const float4*)xrow;

    for (int ch = 0; ch < N_CHUNKS; ch++) {
        const int p = ch & 1;

        // ---- generate A(ch): tanh + Legendre, fp16-packed fragment layout ----
        {
            char* Ab = sm + SMA(p);
            float xf[4] = {xv.x, xv.y, xv.z, xv.w};
            if (ch + 1 < N_CHUNKS) xv = *(const float4*)(xrow + (ch + 1) * 8);

            uint32_t hp[4][4];                         // [feat][c-pair] as half2 bits
            #pragma unroll
            for (int f = 0; f < 4; f++) {
                float e2 = __expf(2.0f * xf[f]);
                float t  = 1.0f - 2.0f / (e2 + 1.0f);
                float pv[8];
                pv[0] = t;
                float pp = 1.0f, pc = t;
                #pragma unroll
                for (int d = 1; d < 8; d++) {
                    float kk = (float)(d + 1);
                    float a_ = (2.0f * kk - 1.0f) / kk;
                    float b_ = (kk - 1.0f) / kk;
                    float pn = a_ * t * pc - b_ * pp;
                    pv[d] = pn; pp = pc; pc = pn;
                }
                #pragma unroll
                for (int cc = 0; cc < 4; cc++) {
                    __half2 h2 = __floats2half2_rn(pv[2 * cc], pv[2 * cc + 1]);
                    hp[f][cc] = *(uint32_t*)&h2;
                }
            }
            // uint4 slot order: [i0-rlow, i1-rlow, i0-rhigh, i1-rhigh]
            // thread (one rh) writes {i0, i1} pair of its ipair as one STS.64
            #pragma unroll
            for (int p2 = 0; p2 < 2; p2++) {
                int ip = half * 2 + p2;
                #pragma unroll
                for (int cc = 0; cc < 4; cc++) {
                    uint2 v = make_uint2(hp[p2 * 2][cc], hp[p2 * 2 + 1][cc]);
                    *(uint2*)(Ab + ((((ip * 4 + cc) * 8 + mt) * 8 + rq) * 16 + rh * 8)) = v;
                }
            }
        }

        // ---- B(ch) arrived + A(ch) visible ----
        asm volatile("cp.async.wait_group 0;" ::: "memory");
        __syncthreads();

        // ---- prefetch B(ch+1) into other buffer (safe: all mma(ch-1) done) ----
        if (ch + 1 < N_CHUNKS) {
            const char* src = (const char*)g_Bpack + (size_t)(ch + 1) * 8192;
            cp_async16(sbase + SMB(p ^ 1) + tid * 16,         src + tid * 16);
            cp_async16(sbase + SMB(p ^ 1) + (tid + 256) * 16, src + (tid + 256) * 16);
            asm volatile("cp.async.commit_group;" ::: "memory");
        }

        // ---- MMA: 4 k-steps x (2 m-tiles x 4 n-tiles) m16n8k16 ----
        {
            const char* Ar = sm + SMA(p);
            const char* Br = sm + SMB(p);
            #pragma unroll
            for (int ks = 0; ks < 4; ks++) {
                uint4 a0 = *(const uint4*)(Ar + (((ks * 4 + c) * 8 + wm * 2 + 0) * 8 + fr) * 16);
                uint4 a1 = *(const uint4*)(Ar + (((ks * 4 + c) * 8 + wm * 2 + 1) * 8 + fr) * 16);
                uint4 b0 = *(const uint4*)(Br + ((ks * 4 + wn * 2 + 0) * 32 + lane) * 16);
                uint4 b1 = *(const uint4*)(Br + ((ks * 4 + wn * 2 + 1) * 32 + lane) * 16);
                // A operand order: (rl-i0, rh-i0, rl-i1, rh-i1) = (x, z, y, w)
                MMA16816(acc[0][0], a0.x, a0.z, a0.y, a0.w, b0.x, b0.y);
                MMA16816(acc[0][1], a0.x, a0.z, a0.y, a0.w, b0.z, b0.w);
                MMA16816(acc[0][2], a0.x, a0.z, a0.y, a0.w, b1.x, b1.y);
                MMA16816(acc[0][3], a0.x, a0.z, a0.y, a0.w, b1.z, b1.w);
                MMA16816(acc[1][0], a1.x, a1.z, a1.y, a1.w, b0.x, b0.y);
                MMA16816(acc[1][1], a1.x, a1.z, a1.y, a1.w, b0.z, b0.w);
                MMA16816(acc[1][2], a1.x, a1.z, a1.y, a1.w, b1.x, b1.y);
                MMA16816(acc[1][3], a1.x, a1.z, a1.y, a1.w, b1.z, b1.w);
            }
        }
    }

    // ---- epilogue: bias + store ----
    #pragma unroll
    for (int t = 0; t < 2; t++) {
        int r0 = rowBase + wm * 32 + t * 16 + fr;
        #pragma unroll
        for (int nt = 0; nt < 4; nt++) {
            int col = wn * 32 + nt * 8 + c * 2;
            float2 bb = *(const float2*)(bias + col);
            if (r0 < batch)
                *(float2*)(y + (size_t)r0 * N_OUT + col) =
                    make_float2(acc[t][nt][0] + bb.x, acc[t][nt][1] + bb.y);
            if (r0 + 8 < batch)
                *(float2*)(y + (size_t)(r0 + 8) * N_OUT + col) =
                    make_float2(acc[t][nt][2] + bb.x, acc[t][nt][3] + bb.y);
        }
    }
}

extern "C" void kernel_launch(void* const* d_in, const int* in_sizes, int n_in,
                              void* d_out, int out_size) {
    const float* x       = (const float*)d_in[0];
    const float* c_basis = (const float*)d_in[1];
    const float* bias    = (const float*)d_in[2];
    float* y = (float*)d_out;
    int batch = in_sizes[0] / N_IN;

    cudaFuncSetAttribute(kan_fp16_kernel,
                         cudaFuncAttributeMaxDynamicSharedMemorySize, SM_TOTAL);

    repack_kernel<<<(N_CHUNKS * 4096) / 256, 256>>>(c_basis);
    int grid = (batch + M_TILE - 1) / M_TILE;
    kan_fp16_kernel<<<grid, 256, SM_TOTAL>>>(x, bias, y, batch);
}

// round 5
// speedup vs baseline: 2.0314x; 1.4902x over previous
#include <cuda_runtime.h>
#include <cuda_fp16.h>
#include <cstdint>

#define N_IN     256
#define DDEG     8
#define N_OUT    64
#define M_TILE   128
#define N_CHUNKS 32

// smem byte offsets: A double-buffered 16KB each, B 8KB each
#define SMA(p)   ((p) * 16384)
#define SMB(p)   (32768 + (p) * 8192)
#define SM_TOTAL 49152

// A-tile in-block swizzle: slot for (fr, c) within a (ks, mtile) 512B block.
// Conflict-free for both the generator's STS.64 and the consumer's LDS.128.
#define ASWZ(fr, c) ((((fr) + 2 * (c)) & 7) + 8 * (c))

// B prepacked as exact per-chunk smem fragment images: 32 chunks x 4096 halves
__device__ __half g_Bpack[N_CHUNKS * 4096];

// Layout: [ch][ks(4)][ng(4)][lane(32)][e(8 halves)]; uint4 slot = frags of
// n-tiles {2ng, 2ng+1}: {nt0.b01, nt0.b23, nt1.b01, nt1.b23}
__global__ void repack_kernel(const float* __restrict__ c_basis) {
    int idx = blockIdx.x * 256 + threadIdx.x;          // 131072 total
    int e    = idx & 7;
    int lane = (idx >> 3) & 31;
    int ng   = (idx >> 8) & 3;
    int ks   = (idx >> 10) & 3;
    int ch   = idx >> 12;
    int nt = ng * 2 + (e >> 2);
    int bp = (e >> 1) & 1;                             // b01 vs b23 (k +8)
    int h  = e & 1;
    int k  = ks * 16 + bp * 8 + (lane & 3) * 2 + h;    // k within chunk
    int n  = nt * 8 + (lane >> 2);
    int kg = ch * 64 + k;
    int i = kg >> 3, d = kg & 7;
    g_Bpack[idx] = __float2half_rn(c_basis[(n * N_IN + i) * DDEG + d]);
}

#define MMA16816(ac, A0, A1, A2, A3, B0, B1)                                  \
    asm volatile(                                                             \
        "mma.sync.aligned.m16n8k16.row.col.f32.f16.f16.f32 "                  \
        "{%0,%1,%2,%3}, {%4,%5,%6,%7}, {%8,%9}, {%0,%1,%2,%3};"               \
        : "+f"((ac)[0]), "+f"((ac)[1]), "+f"((ac)[2]), "+f"((ac)[3])          \
        : "r"(A0), "r"(A1), "r"(A2), "r"(A3), "r"(B0), "r"(B1))

__device__ __forceinline__ void cp_async16(uint32_t saddr, const void* gptr) {
    asm volatile("cp.async.ca.shared.global [%0], [%1], 16;"
                 :: "r"(saddr), "l"(gptr) : "memory");
}

extern __shared__ __align__(128) char sm[];

__global__ __launch_bounds__(256, 2)
void kan_fp16_kernel(const float* __restrict__ x, const float* __restrict__ bias,
                     float* __restrict__ y, int batch) {
    const int tid  = threadIdx.x;
    const int lane = tid & 31;
    const int wid  = tid >> 5;
    const int wm   = wid & 3;          // m32 group (rows wm*32..+31)
    const int wn   = wid >> 2;         // n32 group (cols wn*32..+31)
    const int rowBase = blockIdx.x * M_TILE;
    const uint32_t sbase = (uint32_t)__cvta_generic_to_shared(sm);

    // ---- gen mapping: thread -> (row 0..127, half feats 0-3 / 4-7) ----
    const int grow = tid & 127;
    const int half = tid >> 7;
    const int mt_g = grow >> 4;                  // m-tile of generated row
    const int rh_g = (grow >> 3) & 1;            // low/high row-half of frag
    const int fr_g = grow & 7;                   // fragment row 0..7
    int rg = rowBase + grow; if (rg > batch - 1) rg = batch - 1;
    const float* xrow = x + (size_t)rg * N_IN + half * 4;

    // ---- consumer fragment indices ----
    const int c  = lane & 3;
    const int fr = lane >> 2;

    float acc[2][4][4] = {};

    // ---- prolog: cp.async stage B(0), prefetch x(0) ----
    {
        const char* src = (const char*)g_Bpack;
        cp_async16(sbase + SMB(0) + tid * 16,         src + tid * 16);
        cp_async16(sbase + SMB(0) + (tid + 256) * 16, src + (tid + 256) * 16);
        asm volatile("cp.async.commit_group;" ::: "memory");
    }
    float4 xv = *(const float4*)xrow;

    for (int ch = 0; ch < N_CHUNKS; ch++) {
        const int p = ch & 1;

        // ---- generate A(ch): tanh + Legendre, swizzled fragment layout ----
        {
            char* Ab = sm + SMA(p);
            float xf[4] = {xv.x, xv.y, xv.z, xv.w};
            if (ch + 1 < N_CHUNKS) xv = *(const float4*)(xrow + (ch + 1) * 8);

            uint32_t hp[4][4];                         // [feat][c-pair] half2 bits
            #pragma unroll
            for (int f = 0; f < 4; f++) {
                float e2 = __expf(2.0f * xf[f]);
                float t  = 1.0f - 2.0f / (e2 + 1.0f);
                float pv[8];
                pv[0] = t;
                float pp = 1.0f, pc = t;
                #pragma unroll
                for (int d = 1; d < 8; d++) {
                    float kk = (float)(d + 1);
                    float a_ = (2.0f * kk - 1.0f) / kk;
                    float b_ = (kk - 1.0f) / kk;
                    float pn = a_ * t * pc - b_ * pp;
                    pv[d] = pn; pp = pc; pc = pn;
                }
                #pragma unroll
                for (int cc = 0; cc < 4; cc++) {
                    __half2 h2 = __floats2half2_rn(pv[2 * cc], pv[2 * cc + 1]);
                    hp[f][cc] = *(uint32_t*)&h2;
                }
            }
            // write (i0,i1) pairs: block (ks, mt)*512B, slot ASWZ(fr,c)*16 + rh*8
            #pragma unroll
            for (int p2 = 0; p2 < 2; p2++) {
                int ks = half * 2 + p2;
                char* blk = Ab + (ks * 8 + mt_g) * 512 + rh_g * 8;
                #pragma unroll
                for (int cc = 0; cc < 4; cc++) {
                    uint2 v = make_uint2(hp[p2 * 2][cc], hp[p2 * 2 + 1][cc]);
                    *(uint2*)(blk + ASWZ(fr_g, cc) * 16) = v;
                }
            }
        }

        // ---- B(ch) arrived + A(ch) visible ----
        asm volatile("cp.async.wait_group 0;" ::: "memory");
        __syncthreads();

        // ---- prefetch B(ch+1) (safe: all warps finished MMA(ch-1)) ----
        if (ch + 1 < N_CHUNKS) {
            const char* src = (const char*)g_Bpack + (size_t)(ch + 1) * 8192;
            cp_async16(sbase + SMB(p ^ 1) + tid * 16,         src + tid * 16);
            cp_async16(sbase + SMB(p ^ 1) + (tid + 256) * 16, src + (tid + 256) * 16);
            asm volatile("cp.async.commit_group;" ::: "memory");
        }

        // ---- MMA: 4 k-steps x (2 m-tiles x 4 n-tiles) m16n8k16 ----
        {
            const char* Ar = sm + SMA(p);
            const char* Br = sm + SMB(p);
            #pragma unroll
            for (int ks = 0; ks < 4; ks++) {
                uint4 a0 = *(const uint4*)(Ar + (ks * 8 + wm * 2 + 0) * 512 + ASWZ(fr, c) * 16);
                uint4 a1 = *(const uint4*)(Ar + (ks * 8 + wm * 2 + 1) * 512 + ASWZ(fr, c) * 16);
                uint4 b0 = *(const uint4*)(Br + ((ks * 4 + wn * 2 + 0) * 32 + lane) * 16);
                uint4 b1 = *(const uint4*)(Br + ((ks * 4 + wn * 2 + 1) * 32 + lane) * 16);
                // A operand order: (rl-klo, rh-klo, rl-khi, rh-khi) = (x, z, y, w)
                MMA16816(acc[0][0], a0.x, a0.z, a0.y, a0.w, b0.x, b0.y);
                MMA16816(acc[0][1], a0.x, a0.z, a0.y, a0.w, b0.z, b0.w);
                MMA16816(acc[0][2], a0.x, a0.z, a0.y, a0.w, b1.x, b1.y);
                MMA16816(acc[0][3], a0.x, a0.z, a0.y, a0.w, b1.z, b1.w);
                MMA16816(acc[1][0], a1.x, a1.z, a1.y, a1.w, b0.x, b0.y);
                MMA16816(acc[1][1], a1.x, a1.z, a1.y, a1.w, b0.z, b0.w);
                MMA16816(acc[1][2], a1.x, a1.z, a1.y, a1.w, b1.x, b1.y);
                MMA16816(acc[1][3], a1.x, a1.z, a1.y, a1.w, b1.z, b1.w);
            }
        }
    }

    // ---- epilogue: bias + store ----
    #pragma unroll
    for (int t = 0; t < 2; t++) {
        int r0 = rowBase + wm * 32 + t * 16 + fr;
        #pragma unroll
        for (int nt = 0; nt < 4; nt++) {
            int col = wn * 32 + nt * 8 + c * 2;
            float2 bb = *(const float2*)(bias + col);
            if (r0 < batch)
                *(float2*)(y + (size_t)r0 * N_OUT + col) =
                    make_float2(acc[t][nt][0] + bb.x, acc[t][nt][1] + bb.y);
            if (r0 + 8 < batch)
                *(float2*)(y + (size_t)(r0 + 8) * N_OUT + col) =
                    make_float2(acc[t][nt][2] + bb.x, acc[t][nt][3] + bb.y);
        }
    }
}

extern "C" void kernel_launch(void* const* d_in, const int* in_sizes, int n_in,
                              void* d_out, int out_size) {
    const float* x       = (const float*)d_in[0];
    const float* c_basis = (const float*)d_in[1];
    const float* bias    = (const float*)d_in[2];
    float* y = (float*)d_out;
    int batch = in_sizes[0] / N_IN;

    cudaFuncSetAttribute(kan_fp16_kernel,
                         cudaFuncAttributeMaxDynamicSharedMemorySize, SM_TOTAL);

    repack_kernel<<<(N_CHUNKS * 4096) / 256, 256>>>(c_basis);
    int grid = (batch + M_TILE - 1) / M_TILE;
    kan_fp16_kernel<<<grid, 256, SM_TOTAL>>>(x, bias, y, batch);
}